// round 6
// baseline (speedup 1.0000x reference)
#include <cuda_runtime.h>

#define BB 4
#define HH 512
#define WW 512
#define HW (HH*WW)
#define NPIX (BB*HW)             // 1048576
#define T1 17                    // T_MAX + 1
#define CAP 524352               // NPIX/2 + 64, multiple of 4
#define NCAND 17                 // top-K candidates per target (>= 16 exclusions + 1)

#define NF 1048576.0f
#define SP0F ((float)0.6931471805599453)
#define C1F  ((float)(1.3132616875182228 - 0.6931471805599453))   // SP1 - SP0
#define C2F  ((float)(0.7310585786300049 - 0.5))                  // S1 - 0.5

// ---------------- device scratch (static, no allocation) ----------------
__device__ __align__(16) int g_par[NPIX];     // UF parent; -1 = background
__device__ int g_cidx[NPIX];                  // root pixel -> compact idx
__device__ int g_orig[CAP];                   // compact idx -> root pixel
__device__ int g_cnt_c[CAP];                  // component sizes
__device__ __align__(16) int g_intert[T1 * CAP];  // transposed confusion [t][c]
__device__ int g_cnt_t[T1];
__device__ int g_m;
__device__ float g_bce_sum, g_p_sum, g_pt_sum, g_t_sum;
__device__ unsigned long long g_cand[16][NCAND];  // top-K keys per target t-1

// ---------------- union-find ----------------
// mutating find (path halving) — used only during merge
__device__ __forceinline__ int uf_find(int x) {
    volatile int* par = (volatile int*)g_par;
    int p = par[x];
    while (p != x) {
        int gp = par[p];
        if (gp != p) par[x] = gp;   // halving: stored value always an ancestor
        x = gp;
        p = par[x];
    }
    return x;
}

// read-only find — used during compress
__device__ __forceinline__ int uf_find_ro(int x) {
    const volatile int* par = (const volatile int*)g_par;
    int p = par[x];
    while (p != x) { x = p; p = par[x]; }
    return x;
}

__device__ __forceinline__ void uf_unite(int a, int b) {
    int ra = uf_find(a);
    int rb = uf_find(b);
    while (ra != rb) {
        if (ra > rb) { int t = ra; ra = rb; rb = t; }  // attach smaller under bigger
        int old = atomicMax(&g_par[ra], rb);
        if (old == ra) break;                           // ra was root: linked
        ra = uf_find(old);
        rb = uf_find(rb);
    }
}

// ---------------- block reductions (256-thread blocks, 8 warps) -------------
__device__ __forceinline__ float4 blockReduceSum4(float4 v) {
    __shared__ float4 s[8];
    unsigned m = 0xFFFFFFFFu;
    #pragma unroll
    for (int o = 16; o; o >>= 1) {
        v.x += __shfl_down_sync(m, v.x, o);
        v.y += __shfl_down_sync(m, v.y, o);
        v.z += __shfl_down_sync(m, v.z, o);
        v.w += __shfl_down_sync(m, v.w, o);
    }
    int lane = threadIdx.x & 31, wid = threadIdx.x >> 5;
    if (lane == 0) s[wid] = v;
    __syncthreads();
    if (wid == 0) {
        v = (lane < 8) ? s[lane] : make_float4(0.f, 0.f, 0.f, 0.f);
        #pragma unroll
        for (int o = 4; o; o >>= 1) {
            v.x += __shfl_down_sync(m, v.x, o);
            v.y += __shfl_down_sync(m, v.y, o);
            v.z += __shfl_down_sync(m, v.z, o);
            v.w += __shfl_down_sync(m, v.w, o);
        }
    }
    return v;
}

__device__ __forceinline__ unsigned long long blockReduceMinU64(unsigned long long v) {
    __shared__ unsigned long long s[8];
    unsigned m = 0xFFFFFFFFu;
    #pragma unroll
    for (int o = 16; o; o >>= 1) {
        unsigned long long o2 = __shfl_down_sync(m, v, o);
        v = (o2 < v) ? o2 : v;
    }
    int lane = threadIdx.x & 31, wid = threadIdx.x >> 5;
    if (lane == 0) s[wid] = v;
    __syncthreads();
    if (wid == 0) {
        v = (lane < 8) ? s[lane] : ~0ULL;
        #pragma unroll
        for (int o = 4; o; o >>= 1) {
            unsigned long long o2 = __shfl_down_sync(m, v, o);
            v = (o2 < v) ? o2 : v;
        }
    }
    return v;
}

// ---------------- kernels ----------------
__global__ void init_kernel() {
    int t = threadIdx.x;
    if (t < T1) g_cnt_t[t] = 0;
    if (t == 0) {
        g_bce_sum = 0.f; g_p_sum = 0.f; g_pt_sum = 0.f; g_t_sum = 0.f;
        g_m = 0;
    }
}

// fg + UF init (horizontal run-chaining within quad) + base BCE/Dice + histogram
__global__ void base_kernel(const float* __restrict__ pred, const int* __restrict__ tgt) {
    __shared__ int sbins[T1];
    if (threadIdx.x < T1) sbins[threadIdx.x] = 0;
    __syncthreads();

    int q = blockIdx.x * blockDim.x + threadIdx.x;   // grid covers NPIX/4 exactly
    int i = q << 2;
    int b = i >> 18;
    int hw = i & (HW - 1);
    const float* bp = pred + (size_t)b * 2 * HW;
    float4 p0v = *(const float4*)(bp + hw);
    float4 p1v = *(const float4*)(bp + HW + hw);
    int4 tv = *(const int4*)(tgt + i);
    float a_bce = 0.f, a_p = 0.f, a_pt = 0.f, a_t = 0.f;

    bool f0 = p1v.x > p0v.x, f1 = p1v.y > p0v.y,
         f2 = p1v.z > p0v.z, f3 = p1v.w > p0v.w;

    #define LANE(FG, P1, T) {                                          \
        float y = ((T) > 0) ? 1.f : 0.f;                               \
        if (FG) {                                                      \
            float l = (P1);                                            \
            float e = __expf(-fabsf(l));                               \
            float sp = fmaxf(l, 0.f) + __logf(1.f + e);                \
            float ip = __fdividef(1.f, 1.f + e);                       \
            float p = (l >= 0.f) ? ip : (1.f - ip);                    \
            a_bce += sp - l * y; a_p += p; a_pt += p * y;              \
        } else {                                                       \
            a_bce += SP0F; a_p += 0.5f; a_pt += 0.5f * y;              \
        }                                                              \
        a_t += y;                                                      \
        unsigned mm = __match_any_sync(0xFFFFFFFFu, (T));              \
        if ((__ffs(mm) - 1) == (int)(threadIdx.x & 31))                \
            atomicAdd(&sbins[(T)], __popc(mm));                        \
    }
    LANE(f0, p1v.x, tv.x)
    LANE(f1, p1v.y, tv.y)
    LANE(f2, p1v.z, tv.z)
    LANE(f3, p1v.w, tv.w)
    #undef LANE

    // horizontal run-chaining: parent -> next fg pixel in quad (ancestor, larger idx)
    int4 pv;
    pv.x = f0 ? (f1 ? i + 1 : i + 0) : -1;
    pv.y = f1 ? (f2 ? i + 2 : i + 1) : -1;
    pv.z = f2 ? (f3 ? i + 3 : i + 2) : -1;
    pv.w = f3 ? i + 3 : -1;
    *(int4*)(g_par + i) = pv;

    float4 v = blockReduceSum4(make_float4(a_bce, a_p, a_pt, a_t));
    if (threadIdx.x == 0) {
        atomicAdd(&g_bce_sum, v.x);
        atomicAdd(&g_p_sum,   v.y);
        atomicAdd(&g_pt_sum,  v.z);
        atomicAdd(&g_t_sum,   v.w);
    }
    if (threadIdx.x < T1) atomicAdd(&g_cnt_t[threadIdx.x], sbins[threadIdx.x]);
}

// unites: all vertical edges + horizontal edges across quad boundaries only
__global__ void merge_kernel() {
    int i = blockIdx.x * blockDim.x + threadIdx.x;
    if (g_par[i] < 0) return;
    int w = i & (WW - 1);
    int h = (i >> 9) & (HH - 1);
    if (h > 0 && g_par[i - WW] >= 0) uf_unite(i, i - WW);
    if ((w & 3) == 0 && w > 0 && g_par[i - 1] >= 0) uf_unite(i, i - 1);
}

// flatten to root + block-aggregated compact index assignment (1 px/thread)
__global__ void compress_kernel() {
    __shared__ int s_wbase[8];
    __shared__ int s_blockbase;

    int i = blockIdx.x * blockDim.x + threadIdx.x;
    int p = g_par[i];
    int r = (p < 0) ? -1 : uf_find_ro(i);
    g_par[i] = r;
    int isr = (r == i);

    // warp inclusive scan
    unsigned m = 0xFFFFFFFFu;
    int lane = threadIdx.x & 31, wid = threadIdx.x >> 5;
    int inc = isr;
    #pragma unroll
    for (int o = 1; o < 32; o <<= 1) {
        int v = __shfl_up_sync(m, inc, o);
        if (lane >= o) inc += v;
    }
    if (lane == 31) s_wbase[wid] = inc;
    __syncthreads();
    if (threadIdx.x == 0) {
        int s = 0;
        #pragma unroll
        for (int w = 0; w < 8; w++) { int t = s_wbase[w]; s_wbase[w] = s; s += t; }
        s_blockbase = s ? atomicAdd(&g_m, s) : 0;
    }
    __syncthreads();

    if (isr) {
        int idx = s_blockbase + s_wbase[wid] + (inc - 1);
        g_cidx[i] = idx;
        g_orig[idx] = i;
    }
}

// zero live confusion rows, coalesced (int4)
__global__ void zero_kernel() {
    int M4 = (g_m + 3) >> 2;
    int tot = T1 * M4;
    int stride = gridDim.x * blockDim.x;
    int4 z = make_int4(0, 0, 0, 0);
    for (int j = blockIdx.x * blockDim.x + threadIdx.x; j < tot; j += stride) {
        int t = j / M4, c4 = j - t * M4;
        *(int4*)(g_intert + t * CAP + (c4 << 2)) = z;
    }
}

// confusion counts with warp aggregation (g_par entries are exact roots here)
__global__ void build_kernel(const int* __restrict__ tgt) {
    int i = blockIdx.x * blockDim.x + threadIdx.x;
    int r = g_par[i];
    int t = tgt[i];
    bool fg = r >= 0;
    int c = fg ? g_cidx[r] : 0;
    int key = fg ? (c * T1 + t) : -(int)(threadIdx.x & 31) - 1;
    unsigned mm = __match_any_sync(0xFFFFFFFFu, key);
    if (fg && (__ffs(mm) - 1) == (int)(threadIdx.x & 31))
        atomicAdd(&g_intert[t * CAP + c], __popc(mm));
}

// component sizes = row sums (coalesced)
__global__ void cntc_kernel() {
    int M = g_m;
    int stride = gridDim.x * blockDim.x;
    for (int c = blockIdx.x * blockDim.x + threadIdx.x; c < M; c += stride) {
        int s = 0;
        #pragma unroll
        for (int t = 0; t < T1; t++) s += g_intert[t * CAP + c];
        g_cnt_c[c] = s;
    }
}

// ONE launch: per target t, compute top-NCAND candidate keys (no exclusions)
// grid = 16 blocks (one per t), 256 threads
__global__ void cand_kernel() {
    const int t = blockIdx.x + 1;
    const int M = g_m;
    const float ct = (float)g_cnt_t[t];
    __shared__ unsigned long long s_min;

    unsigned long long loc[NCAND];
    #pragma unroll
    for (int k = 0; k < NCAND; k++) loc[k] = ~0ULL;

    for (int c = threadIdx.x; c < M; c += 256) {
        float cnt_p = (float)g_cnt_c[c];
        float it = (float)g_intert[t * CAP + c];
        float bce = (NF * SP0F + cnt_p * C1F - it) / NF;
        float sum_pt = 0.5f * ct + C2F * it;
        float sum_p  = 0.5f * NF + C2F * cnt_p;
        float dice = 1.f - (2.f * sum_pt + 1.f) / ((sum_p + ct) + 1.f);
        float loss = bce + dice;
        unsigned long long key =
            ((unsigned long long)__float_as_uint(loss) << 32) | (unsigned)g_orig[c];
        if (key < loc[NCAND - 1]) {
            int k = NCAND - 1;
            while (k > 0 && loc[k - 1] > key) { loc[k] = loc[k - 1]; k--; }
            loc[k] = key;
        }
    }

    // block merge: NCAND rounds of (min over thread heads, pop winner)
    int ptr = 0;
    for (int k = 0; k < NCAND; k++) {
        unsigned long long v = (ptr < NCAND) ? loc[ptr] : ~0ULL;
        unsigned long long mn = blockReduceMinU64(v);
        if (threadIdx.x == 0) s_min = mn;
        __syncthreads();
        mn = s_min;
        if (ptr < NCAND && loc[ptr] == mn && mn != ~0ULL) ptr++;   // unique keys
        if (threadIdx.x == 0) g_cand[blockIdx.x][k] = mn;
        __syncthreads();
    }
}

// serial greedy replay over candidate lists + assemble final scalar
__global__ void final_kernel(float* __restrict__ out) {
    float acc = 0.f, matched = 0.f, untgt = 0.f;
    unsigned uo[16];
    int un = 0;
    for (int t = 1; t < T1; t++) {
        bool present = g_cnt_t[t] > 0;
        unsigned long long pick = ~0ULL;
        for (int k = 0; k < NCAND; k++) {
            unsigned long long cnd = g_cand[t - 1][k];
            if (cnd == ~0ULL) break;
            unsigned o = (unsigned)(cnd & 0xFFFFFFFFu);
            bool bad = false;
            for (int u = 0; u < un; u++) bad |= (uo[u] == o);
            if (!bad) { pick = cnd; break; }
        }
        if (present && pick != ~0ULL) {
            acc += __uint_as_float((unsigned)(pick >> 32));
            uo[un++] = (unsigned)(pick & 0xFFFFFFFFu);
            matched += 1.f;
        } else if (present) {
            untgt += 1.f;
        }
    }
    float bce = g_bce_sum / NF;
    float dice = 1.f - (2.f * g_pt_sum + 1.f) / ((g_p_sum + g_t_sum) + 1.f);
    out[0] = (bce + dice) + acc + ((float)g_m - matched) + untgt;
}

// ---------------- launch ----------------
extern "C" void kernel_launch(void* const* d_in, const int* in_sizes, int n_in,
                              void* d_out, int out_size) {
    const float* pred = (const float*)d_in[0];   // [4,2,512,512] f32
    const int*   tgt  = (const int*)d_in[1];     // [4,1,512,512] i32
    float* out = (float*)d_out;

    init_kernel<<<1, 32>>>();
    base_kernel<<<NPIX / 4 / 256, 256>>>(pred, tgt);
    merge_kernel<<<NPIX / 256, 256>>>();
    compress_kernel<<<NPIX / 256, 256>>>();
    zero_kernel<<<512, 256>>>();
    build_kernel<<<NPIX / 256, 256>>>(tgt);
    cntc_kernel<<<256, 256>>>();
    cand_kernel<<<16, 256>>>();
    final_kernel<<<1, 1>>>(out);
}

// round 7
// speedup vs baseline: 3.5985x; 3.5985x over previous
#include <cuda_runtime.h>

#define BB 4
#define HH 512
#define WW 512
#define HW (HH*WW)
#define NPIX (BB*HW)             // 1048576
#define T1 17                    // T_MAX + 1
#define CAP 524352               // NPIX/2 + 64, multiple of 4

#define NF 1048576.0f
#define SP0F ((float)0.6931471805599453)
#define C1F  ((float)(1.3132616875182228 - 0.6931471805599453))   // SP1 - SP0
#define C2F  ((float)(0.7310585786300049 - 0.5))                  // S1 - 0.5

// ---------------- device scratch (static, no allocation) ----------------
__device__ __align__(16) int g_par[NPIX];     // UF parent; -1 = background
__device__ int g_cidx[NPIX];                  // root pixel -> compact idx
__device__ int g_orig[CAP];                   // compact idx -> root pixel
__device__ int g_cnt_c[CAP];                  // component sizes
__device__ __align__(16) int g_intert[T1 * CAP];  // transposed confusion [t][c]
__device__ int g_cnt_t[T1];
__device__ int g_m;
__device__ float g_bce_sum, g_p_sum, g_pt_sum, g_t_sum;
__device__ unsigned long long g_mk[T1];

// ---------------- union-find ----------------
// mutating find (path halving) — used only during merge
__device__ __forceinline__ int uf_find(int x) {
    volatile int* par = (volatile int*)g_par;
    int p = par[x];
    while (p != x) {
        int gp = par[p];
        if (gp != p) par[x] = gp;   // halving: stored value always an ancestor
        x = gp;
        p = par[x];
    }
    return x;
}

// read-only find — used during compress (no stores => final g_par stores are roots)
__device__ __forceinline__ int uf_find_ro(int x) {
    const volatile int* par = (const volatile int*)g_par;
    int p = par[x];
    while (p != x) { x = p; p = par[x]; }
    return x;
}

__device__ __forceinline__ void uf_unite(int a, int b) {
    int ra = uf_find(a);
    int rb = uf_find(b);
    while (ra != rb) {
        if (ra > rb) { int t = ra; ra = rb; rb = t; }  // attach smaller under bigger
        int old = atomicMax(&g_par[ra], rb);
        if (old == ra) break;                           // ra was root: linked
        ra = uf_find(old);
        rb = uf_find(rb);
    }
}

// ---------------- block reductions (256-thread blocks, 8 warps) -------------
__device__ __forceinline__ float4 blockReduceSum4(float4 v) {
    __shared__ float4 s[8];
    unsigned m = 0xFFFFFFFFu;
    #pragma unroll
    for (int o = 16; o; o >>= 1) {
        v.x += __shfl_down_sync(m, v.x, o);
        v.y += __shfl_down_sync(m, v.y, o);
        v.z += __shfl_down_sync(m, v.z, o);
        v.w += __shfl_down_sync(m, v.w, o);
    }
    int lane = threadIdx.x & 31, wid = threadIdx.x >> 5;
    if (lane == 0) s[wid] = v;
    __syncthreads();
    if (wid == 0) {
        v = (lane < 8) ? s[lane] : make_float4(0.f, 0.f, 0.f, 0.f);
        #pragma unroll
        for (int o = 4; o; o >>= 1) {
            v.x += __shfl_down_sync(m, v.x, o);
            v.y += __shfl_down_sync(m, v.y, o);
            v.z += __shfl_down_sync(m, v.z, o);
            v.w += __shfl_down_sync(m, v.w, o);
        }
    }
    return v;
}

__device__ __forceinline__ unsigned long long blockReduceMinU64(unsigned long long v) {
    __shared__ unsigned long long s[8];
    unsigned m = 0xFFFFFFFFu;
    #pragma unroll
    for (int o = 16; o; o >>= 1) {
        unsigned long long o2 = __shfl_down_sync(m, v, o);
        v = (o2 < v) ? o2 : v;
    }
    int lane = threadIdx.x & 31, wid = threadIdx.x >> 5;
    if (lane == 0) s[wid] = v;
    __syncthreads();
    if (wid == 0) {
        v = (lane < 8) ? s[lane] : ~0ULL;
        #pragma unroll
        for (int o = 4; o; o >>= 1) {
            unsigned long long o2 = __shfl_down_sync(m, v, o);
            v = (o2 < v) ? o2 : v;
        }
    }
    return v;
}

// ---------------- kernels ----------------
__global__ void init_kernel() {
    int t = threadIdx.x;
    if (t < T1) { g_cnt_t[t] = 0; g_mk[t] = ~0ULL; }
    if (t == 0) {
        g_bce_sum = 0.f; g_p_sum = 0.f; g_pt_sum = 0.f; g_t_sum = 0.f;
        g_m = 0;
    }
}

// fg + UF init + base BCE/Dice partials + target histogram (1 quad / thread)
__global__ void base_kernel(const float* __restrict__ pred, const int* __restrict__ tgt) {
    __shared__ int sbins[T1];
    if (threadIdx.x < T1) sbins[threadIdx.x] = 0;
    __syncthreads();

    int q = blockIdx.x * blockDim.x + threadIdx.x;   // grid covers NPIX/4 exactly
    int i = q << 2;
    int b = i >> 18;
    int hw = i & (HW - 1);
    const float* bp = pred + (size_t)b * 2 * HW;
    float4 p0v = *(const float4*)(bp + hw);
    float4 p1v = *(const float4*)(bp + HW + hw);
    int4 tv = *(const int4*)(tgt + i);
    int4 pv;
    float a_bce = 0.f, a_p = 0.f, a_pt = 0.f, a_t = 0.f;

    #define LANE(P0, P1, T, IDX, POUT) {                               \
        bool fg = (P1) > (P0);                                         \
        float y = ((T) > 0) ? 1.f : 0.f;                               \
        if (fg) {                                                      \
            float l = (P1);                                            \
            float e = __expf(-fabsf(l));                               \
            float sp = fmaxf(l, 0.f) + __logf(1.f + e);                \
            float ip = __fdividef(1.f, 1.f + e);                       \
            float p = (l >= 0.f) ? ip : (1.f - ip);                    \
            a_bce += sp - l * y; a_p += p; a_pt += p * y;              \
        } else {                                                       \
            a_bce += SP0F; a_p += 0.5f; a_pt += 0.5f * y;              \
        }                                                              \
        a_t += y;                                                      \
        POUT = fg ? (IDX) : -1;                                        \
        unsigned mm = __match_any_sync(0xFFFFFFFFu, (T));              \
        if ((__ffs(mm) - 1) == (int)(threadIdx.x & 31))                \
            atomicAdd(&sbins[(T)], __popc(mm));                        \
    }
    LANE(p0v.x, p1v.x, tv.x, i + 0, pv.x)
    LANE(p0v.y, p1v.y, tv.y, i + 1, pv.y)
    LANE(p0v.z, p1v.z, tv.z, i + 2, pv.z)
    LANE(p0v.w, p1v.w, tv.w, i + 3, pv.w)
    #undef LANE
    *(int4*)(g_par + i) = pv;

    float4 v = blockReduceSum4(make_float4(a_bce, a_p, a_pt, a_t));
    if (threadIdx.x == 0) {
        atomicAdd(&g_bce_sum, v.x);
        atomicAdd(&g_p_sum,   v.y);
        atomicAdd(&g_pt_sum,  v.z);
        atomicAdd(&g_t_sum,   v.w);
    }
    if (threadIdx.x < T1) atomicAdd(&g_cnt_t[threadIdx.x], sbins[threadIdx.x]);
}

// union over left & up edges (per image); 1 pixel / thread
__global__ void merge_kernel() {
    int i = blockIdx.x * blockDim.x + threadIdx.x;
    if (g_par[i] < 0) return;
    int w = i & (WW - 1);
    int h = (i >> 9) & (HH - 1);
    if (w > 0 && g_par[i - 1]  >= 0) uf_unite(i, i - 1);
    if (h > 0 && g_par[i - WW] >= 0) uf_unite(i, i - WW);
}

// flatten to root + block-aggregated compact index assignment (1 px/thread)
// (one atomicAdd(&g_m) per block instead of one per root — measured 15.6us in R6)
__global__ void compress_kernel() {
    __shared__ int s_wbase[8];
    __shared__ int s_blockbase;

    int i = blockIdx.x * blockDim.x + threadIdx.x;
    int p = g_par[i];
    int r = (p < 0) ? -1 : uf_find_ro(i);
    g_par[i] = r;
    int isr = (r == i);

    // warp inclusive scan
    unsigned m = 0xFFFFFFFFu;
    int lane = threadIdx.x & 31, wid = threadIdx.x >> 5;
    int inc = isr;
    #pragma unroll
    for (int o = 1; o < 32; o <<= 1) {
        int v = __shfl_up_sync(m, inc, o);
        if (lane >= o) inc += v;
    }
    if (lane == 31) s_wbase[wid] = inc;
    __syncthreads();
    if (threadIdx.x == 0) {
        int s = 0;
        #pragma unroll
        for (int w = 0; w < 8; w++) { int t = s_wbase[w]; s_wbase[w] = s; s += t; }
        s_blockbase = s ? atomicAdd(&g_m, s) : 0;
    }
    __syncthreads();

    if (isr) {
        int idx = s_blockbase + s_wbase[wid] + (inc - 1);
        g_cidx[i] = idx;
        g_orig[idx] = i;
    }
}

// zero live confusion rows, coalesced (int4)
__global__ void zero_kernel() {
    int M4 = (g_m + 3) >> 2;
    int tot = T1 * M4;
    int stride = gridDim.x * blockDim.x;
    int4 z = make_int4(0, 0, 0, 0);
    for (int j = blockIdx.x * blockDim.x + threadIdx.x; j < tot; j += stride) {
        int t = j / M4, c4 = j - t * M4;
        *(int4*)(g_intert + t * CAP + (c4 << 2)) = z;
    }
}

// confusion counts with warp aggregation (g_par entries are exact roots here)
__global__ void build_kernel(const int* __restrict__ tgt) {
    int i = blockIdx.x * blockDim.x + threadIdx.x;
    int r = g_par[i];
    int t = tgt[i];
    bool fg = r >= 0;
    int c = fg ? g_cidx[r] : 0;
    int key = fg ? (c * T1 + t) : -(int)(threadIdx.x & 31) - 1;
    unsigned mm = __match_any_sync(0xFFFFFFFFu, key);
    if (fg && (__ffs(mm) - 1) == (int)(threadIdx.x & 31))
        atomicAdd(&g_intert[t * CAP + c], __popc(mm));
}

// component sizes = row sums (coalesced)
__global__ void cntc_kernel() {
    int M = g_m;
    int stride = gridDim.x * blockDim.x;
    for (int c = blockIdx.x * blockDim.x + threadIdx.x; c < M; c += stride) {
        int s = 0;
        #pragma unroll
        for (int t = 0; t < T1; t++) s += g_intert[t * CAP + c];
        g_cnt_c[c] = s;
    }
}

// greedy round t: reconstruct used set from prior g_mk, scan, atomicMin winner
__global__ void argmin_kernel(int t) {
    __shared__ int s_uo[16];
    __shared__ int s_un;
    if (threadIdx.x == 0) {
        int un = 0;
        for (int s = 1; s < t; s++) {
            unsigned long long k = g_mk[s];
            if (g_cnt_t[s] > 0 && k != ~0ULL)
                s_uo[un++] = (int)(unsigned)(k & 0xFFFFFFFFu);
        }
        s_un = un;
    }
    __syncthreads();
    const int un = s_un;
    const int M = g_m;
    const float ct = (float)g_cnt_t[t];
    const int stride = gridDim.x * blockDim.x;
    unsigned long long best = ~0ULL;
    for (int c = blockIdx.x * blockDim.x + threadIdx.x; c < M; c += stride) {
        int orig = g_orig[c];
        bool skip = false;
        for (int u = 0; u < un; u++) skip |= (s_uo[u] == orig);
        if (!skip) {
            float cnt_p = (float)g_cnt_c[c];
            float it = (float)g_intert[t * CAP + c];
            float bce = (NF * SP0F + cnt_p * C1F - it) / NF;
            float sum_pt = 0.5f * ct + C2F * it;
            float sum_p  = 0.5f * NF + C2F * cnt_p;
            float dice = 1.f - (2.f * sum_pt + 1.f) / ((sum_p + ct) + 1.f);
            float loss = bce + dice;
            unsigned long long key =
                ((unsigned long long)__float_as_uint(loss) << 32) | (unsigned)orig;
            best = (key < best) ? key : best;
        }
    }
    best = blockReduceMinU64(best);
    if (threadIdx.x == 0 && best != ~0ULL) atomicMin(&g_mk[t], best);
}

// replay greedy decisions + assemble final scalar
__global__ void final_kernel(float* __restrict__ out) {
    float acc = 0.f, matched = 0.f, untgt = 0.f;
    #pragma unroll
    for (int t = 1; t < T1; t++) {
        unsigned long long k = g_mk[t];
        bool present = g_cnt_t[t] > 0;
        bool avail = (k != ~0ULL);
        if (present && avail) {
            acc += __uint_as_float((unsigned)(k >> 32));
            matched += 1.f;
        } else if (present) {
            untgt += 1.f;
        }
    }
    float bce = g_bce_sum / NF;
    float dice = 1.f - (2.f * g_pt_sum + 1.f) / ((g_p_sum + g_t_sum) + 1.f);
    out[0] = (bce + dice) + acc + ((float)g_m - matched) + untgt;
}

// ---------------- launch ----------------
extern "C" void kernel_launch(void* const* d_in, const int* in_sizes, int n_in,
                              void* d_out, int out_size) {
    const float* pred = (const float*)d_in[0];   // [4,2,512,512] f32
    const int*   tgt  = (const int*)d_in[1];     // [4,1,512,512] i32
    float* out = (float*)d_out;

    init_kernel<<<1, 32>>>();
    base_kernel<<<NPIX / 4 / 256, 256>>>(pred, tgt);
    merge_kernel<<<NPIX / 256, 256>>>();
    compress_kernel<<<NPIX / 256, 256>>>();
    zero_kernel<<<512, 256>>>();
    build_kernel<<<NPIX / 256, 256>>>(tgt);
    cntc_kernel<<<256, 256>>>();

    for (int t = 1; t < T1; t++)
        argmin_kernel<<<128, 256>>>(t);
    final_kernel<<<1, 1>>>(out);
}